// round 1
// baseline (speedup 1.0000x reference)
#include <cuda_runtime.h>
#include <cuda_bf16.h>
#include <math.h>

// ---------------------------------------------------------------------------
// Problem constants
// ---------------------------------------------------------------------------
#define N_SRC0   262144
#define N_DST0   65536
#define N_DST1   8192
#define HID      128
#define N_CATS   9
#define CAT_VOCAB 101
#define CAT_DIM  16
#define GENRE_DIM 20
#define K_PROJ   164      // 9*16 + 20
#define NE0      1048576
#define NE1      131072
#define NP       8192     // pos/neg pairs
#define NS       16384    // total scores

// ---------------------------------------------------------------------------
// Static device scratch (allocation-free rule: use __device__ globals)
// ---------------------------------------------------------------------------
__device__ float g_h[(size_t)N_SRC0 * HID];      // projected features
__device__ float g_n[(size_t)N_SRC0 * HID];      // relu(h @ Q) (reused layer 1)
__device__ float g_agg0[(size_t)N_DST0 * HID];
__device__ float g_ws0[N_DST0];
__device__ float g_inv0[N_DST0];
__device__ float g_h1[(size_t)N_DST0 * HID];
__device__ float g_agg1[(size_t)N_DST1 * HID];
__device__ float g_ws1[N_DST1];
__device__ float g_inv1[N_DST1];
__device__ float g_hitem[(size_t)N_DST1 * HID];
__device__ float g_scores[NS];
__device__ unsigned int g_rank_sum;

// ---------------------------------------------------------------------------
// Utility kernels
// ---------------------------------------------------------------------------
__global__ void zero_f_kernel(float* p, int n) {
    int i = blockIdx.x * blockDim.x + threadIdx.x;
    int stride = gridDim.x * blockDim.x;
    for (; i < n; i += stride) p[i] = 0.0f;
}

__global__ void zero_u32_kernel(unsigned int* p) { *p = 0u; }

__global__ void invws_kernel(const float* __restrict__ ws, float* __restrict__ inv, int n) {
    int i = blockIdx.x * blockDim.x + threadIdx.x;
    if (i < n) inv[i] = 1.0f / fmaxf(ws[i], 1.0f);
}

// ---------------------------------------------------------------------------
// GEMM tiling config: 64 x 128 tile, BK=16, 256 threads, 8x4 micro-tile
// ---------------------------------------------------------------------------
#define BM 64
#define BN 128
#define BK 16

// ---- proj kernel: h = feats @ fc_W + fc_b + track_emb[ids]  (K=164) -------
__global__ __launch_bounds__(256)
void proj_kernel(const int* __restrict__ ids,
                 const int* __restrict__ cats,
                 const float* __restrict__ genre,
                 const float* __restrict__ cat_embs,  // [9][101][16]
                 const float* __restrict__ W,          // [164][128]
                 const float* __restrict__ bvec,       // [128]
                 const float* __restrict__ track_emb,  // [1e6][128]
                 float* __restrict__ out) {
    __shared__ float As[BK][BM];
    __shared__ float Ws[BK][BN];
    __shared__ int   sIds[BM];

    int tid = threadIdx.x;
    int tx = tid & 31, ty = tid >> 5;
    int r0 = blockIdx.x * BM;

    if (tid < BM) sIds[tid] = ids[r0 + tid];

    float acc[8][4] = {};

    for (int k0 = 0; k0 < K_PROJ; k0 += BK) {
        // ---- A tile (feats, built on the fly) ----
        {
            int row = tid >> 2;
            int kq = (tid & 3) * 4;
            int r = r0 + row;
            int kbase = k0 + kq;
            #pragma unroll
            for (int j = 0; j < 4; j++) {
                int kg = kbase + j;
                float v = 0.0f;
                if (kg < 144) {
                    int c = kg >> 4, d = kg & 15;
                    int cid = cats[r * N_CATS + c];
                    v = cat_embs[((c * CAT_VOCAB) + cid) * CAT_DIM + d];
                } else if (kg < K_PROJ) {
                    v = genre[(size_t)r * GENRE_DIM + (kg - 144)];
                }
                As[kq + j][row] = v;
            }
        }
        // ---- W tile ----
        {
            int k = tid >> 4;
            int n = (tid & 15) * 8;
            int kg = k0 + k;
            if (kg < K_PROJ) {
                float4 v0 = *(const float4*)&W[kg * 128 + n];
                float4 v1 = *(const float4*)&W[kg * 128 + n + 4];
                *(float4*)&Ws[k][n] = v0;
                *(float4*)&Ws[k][n + 4] = v1;
            } else {
                float4 z = {0.f, 0.f, 0.f, 0.f};
                *(float4*)&Ws[k][n] = z;
                *(float4*)&Ws[k][n + 4] = z;
            }
        }
        __syncthreads();
        #pragma unroll
        for (int kk = 0; kk < BK; kk++) {
            float4 b4 = *(float4*)&Ws[kk][tx * 4];
            float4 a0 = *(float4*)&As[kk][ty * 8];
            float4 a1 = *(float4*)&As[kk][ty * 8 + 4];
            float ar[8] = {a0.x, a0.y, a0.z, a0.w, a1.x, a1.y, a1.z, a1.w};
            float bc[4] = {b4.x, b4.y, b4.z, b4.w};
            #pragma unroll
            for (int r = 0; r < 8; r++)
                #pragma unroll
                for (int c = 0; c < 4; c++)
                    acc[r][c] += ar[r] * bc[c];
        }
        __syncthreads();
    }

    float4 bb = *(const float4*)&bvec[tx * 4];
    float bv[4] = {bb.x, bb.y, bb.z, bb.w};
    #pragma unroll
    for (int r = 0; r < 8; r++) {
        int lrow = ty * 8 + r;
        size_t row = (size_t)(r0 + lrow);
        long id = sIds[lrow];
        float4 te = *(const float4*)&track_emb[(size_t)id * 128 + tx * 4];
        float4 o;
        o.x = acc[r][0] + bv[0] + te.x;
        o.y = acc[r][1] + bv[1] + te.y;
        o.z = acc[r][2] + bv[2] + te.z;
        o.w = acc[r][3] + bv[3] + te.w;
        *(float4*)&out[row * 128 + tx * 4] = o;
    }
}

// ---- Q GEMM: out = relu(A @ W + b), K = 128 --------------------------------
__global__ __launch_bounds__(256)
void gemm_q_kernel(const float* __restrict__ A,
                   const float* __restrict__ W,
                   const float* __restrict__ bvec,
                   float* __restrict__ out) {
    __shared__ float As[BK][BM];
    __shared__ float Ws[BK][BN];

    int tid = threadIdx.x;
    int tx = tid & 31, ty = tid >> 5;
    int r0 = blockIdx.x * BM;

    float acc[8][4] = {};
    const int K = 128;

    for (int k0 = 0; k0 < K; k0 += BK) {
        {
            int row = tid >> 2;
            int kq = (tid & 3) * 4;
            float4 v = *(const float4*)&A[(size_t)(r0 + row) * K + k0 + kq];
            As[kq + 0][row] = v.x; As[kq + 1][row] = v.y;
            As[kq + 2][row] = v.z; As[kq + 3][row] = v.w;
        }
        {
            int k = tid >> 4;
            int n = (tid & 15) * 8;
            float4 v0 = *(const float4*)&W[(k0 + k) * 128 + n];
            float4 v1 = *(const float4*)&W[(k0 + k) * 128 + n + 4];
            *(float4*)&Ws[k][n] = v0;
            *(float4*)&Ws[k][n + 4] = v1;
        }
        __syncthreads();
        #pragma unroll
        for (int kk = 0; kk < BK; kk++) {
            float4 b4 = *(float4*)&Ws[kk][tx * 4];
            float4 a0 = *(float4*)&As[kk][ty * 8];
            float4 a1 = *(float4*)&As[kk][ty * 8 + 4];
            float ar[8] = {a0.x, a0.y, a0.z, a0.w, a1.x, a1.y, a1.z, a1.w};
            float bc[4] = {b4.x, b4.y, b4.z, b4.w};
            #pragma unroll
            for (int r = 0; r < 8; r++)
                #pragma unroll
                for (int c = 0; c < 4; c++)
                    acc[r][c] += ar[r] * bc[c];
        }
        __syncthreads();
    }

    float4 bb = *(const float4*)&bvec[tx * 4];
    float bv[4] = {bb.x, bb.y, bb.z, bb.w};
    #pragma unroll
    for (int r = 0; r < 8; r++) {
        size_t row = (size_t)(r0 + ty * 8 + r);
        float4 o;
        o.x = fmaxf(acc[r][0] + bv[0], 0.f);
        o.y = fmaxf(acc[r][1] + bv[1], 0.f);
        o.z = fmaxf(acc[r][2] + bv[2], 0.f);
        o.w = fmaxf(acc[r][3] + bv[3], 0.f);
        *(float4*)&out[row * 128 + tx * 4] = o;
    }
}

// ---- edge aggregation: agg[dst] += n[src]*w, ws[dst] += w ------------------
__global__ __launch_bounds__(256)
void edge_agg_kernel(const float* __restrict__ nmat,
                     const int* __restrict__ es,
                     const int* __restrict__ ed,
                     const float* __restrict__ w,
                     float* __restrict__ agg,
                     float* __restrict__ ws,
                     int nE) {
    int wid = (blockIdx.x * blockDim.x + threadIdx.x) >> 5;
    int lane = threadIdx.x & 31;
    if (wid >= nE) return;
    int s = es[wid];
    int d = ed[wid];
    float wt = w[wid];
    float4 v = *(const float4*)&nmat[(size_t)s * 128 + lane * 4];
    float* dst = &agg[(size_t)d * 128 + lane * 4];
    atomicAdd(dst + 0, v.x * wt);
    atomicAdd(dst + 1, v.y * wt);
    atomicAdd(dst + 2, v.z * wt);
    atomicAdd(dst + 3, v.w * wt);
    if (lane == 0) atomicAdd(&ws[d], wt);
}

// ---- W GEMM + row-normalize: out = norm(relu([agg*inv, hdst] @ W + b)) -----
// K = 256. Optional residual add (addsrc) for the final layer.
__global__ __launch_bounds__(256)
void gemm_wnorm_kernel(const float* __restrict__ agg,
                       const float* __restrict__ inv,
                       const float* __restrict__ hdst,
                       const float* __restrict__ W,   // [256][128]
                       const float* __restrict__ bvec,
                       const float* __restrict__ addsrc,  // may be null
                       float* __restrict__ out) {
    __shared__ float As[BK][BM];
    __shared__ float Ws[BK][BN];

    int tid = threadIdx.x;
    int tx = tid & 31, ty = tid >> 5;
    int r0 = blockIdx.x * BM;

    float acc[8][4] = {};
    const int K = 256;

    for (int k0 = 0; k0 < K; k0 += BK) {
        {
            int row = tid >> 2;
            int kq = (tid & 3) * 4;
            int r = r0 + row;
            int kg = k0 + kq;
            float4 v;
            if (kg < 128) {
                float iw = inv[r];
                v = *(const float4*)&agg[(size_t)r * 128 + kg];
                v.x *= iw; v.y *= iw; v.z *= iw; v.w *= iw;
            } else {
                v = *(const float4*)&hdst[(size_t)r * 128 + (kg - 128)];
            }
            As[kq + 0][row] = v.x; As[kq + 1][row] = v.y;
            As[kq + 2][row] = v.z; As[kq + 3][row] = v.w;
        }
        {
            int k = tid >> 4;
            int n = (tid & 15) * 8;
            float4 v0 = *(const float4*)&W[(k0 + k) * 128 + n];
            float4 v1 = *(const float4*)&W[(k0 + k) * 128 + n + 4];
            *(float4*)&Ws[k][n] = v0;
            *(float4*)&Ws[k][n + 4] = v1;
        }
        __syncthreads();
        #pragma unroll
        for (int kk = 0; kk < BK; kk++) {
            float4 b4 = *(float4*)&Ws[kk][tx * 4];
            float4 a0 = *(float4*)&As[kk][ty * 8];
            float4 a1 = *(float4*)&As[kk][ty * 8 + 4];
            float ar[8] = {a0.x, a0.y, a0.z, a0.w, a1.x, a1.y, a1.z, a1.w};
            float bc[4] = {b4.x, b4.y, b4.z, b4.w};
            #pragma unroll
            for (int r = 0; r < 8; r++)
                #pragma unroll
                for (int c = 0; c < 4; c++)
                    acc[r][c] += ar[r] * bc[c];
        }
        __syncthreads();
    }

    float4 bb = *(const float4*)&bvec[tx * 4];
    float bv[4] = {bb.x, bb.y, bb.z, bb.w};
    #pragma unroll
    for (int r = 0; r < 8; r++) {
        float z0 = fmaxf(acc[r][0] + bv[0], 0.f);
        float z1 = fmaxf(acc[r][1] + bv[1], 0.f);
        float z2 = fmaxf(acc[r][2] + bv[2], 0.f);
        float z3 = fmaxf(acc[r][3] + bv[3], 0.f);
        float ss = z0 * z0 + z1 * z1 + z2 * z2 + z3 * z3;
        // full-warp reduce over tx (ty is constant within a warp)
        #pragma unroll
        for (int off = 16; off > 0; off >>= 1)
            ss += __shfl_xor_sync(0xffffffffu, ss, off);
        float invn = (ss > 0.f) ? rsqrtf(ss) : 1.0f;
        size_t row = (size_t)(r0 + ty * 8 + r);
        float4 o;
        o.x = z0 * invn; o.y = z1 * invn; o.z = z2 * invn; o.w = z3 * invn;
        if (addsrc) {
            float4 a = *(const float4*)&addsrc[row * 128 + tx * 4];
            o.x += a.x; o.y += a.y; o.z += a.z; o.w += a.w;
        }
        *(float4*)&out[row * 128 + tx * 4] = o;
    }
}

// ---- scores: one warp per (src,dst) pair -----------------------------------
__global__ __launch_bounds__(256)
void score_kernel(const float* __restrict__ hi,
                  const int* __restrict__ ps, const int* __restrict__ pd,
                  const int* __restrict__ ns, const int* __restrict__ nd,
                  const int* __restrict__ nids,
                  const float* __restrict__ bias,
                  float* __restrict__ scores) {
    int wid = (blockIdx.x * blockDim.x + threadIdx.x) >> 5;
    int lane = threadIdx.x & 31;
    if (wid >= NS) return;
    int s, d;
    if (wid < NP) { s = ps[wid]; d = pd[wid]; }
    else          { s = ns[wid - NP]; d = nd[wid - NP]; }
    float4 a = *(const float4*)&hi[(size_t)s * 128 + lane * 4];
    float4 b = *(const float4*)&hi[(size_t)d * 128 + lane * 4];
    float p = a.x * b.x + a.y * b.y + a.z * b.z + a.w * b.w;
    #pragma unroll
    for (int off = 16; off > 0; off >>= 1)
        p += __shfl_xor_sync(0xffffffffu, p, off);
    if (lane == 0)
        scores[wid] = p + bias[nids[s]] + bias[nids[d]];
}

// ---- loss ------------------------------------------------------------------
__global__ void loss_kernel(const float* __restrict__ scores, float* __restrict__ out) {
    int i = blockIdx.x * blockDim.x + threadIdx.x;
    if (i < NP)
        out[i] = fmaxf(scores[NP + i] - scores[i] + 1.0f, 0.0f);
}

// ---- AUC: sum of stable-sort ranks of positives ----------------------------
// rank_i = #{j : s_j < s_i} + #{j < i : s_j == s_i}  (stable sort, pos-first order)
__global__ __launch_bounds__(256)
void auc_count_kernel(const float* __restrict__ scores, unsigned int* __restrict__ R) {
    extern __shared__ float ss[];
    int tid = threadIdx.x;
    for (int j = tid; j < NS; j += blockDim.x) ss[j] = scores[j];
    __syncthreads();
    int i = blockIdx.x * blockDim.x + tid;   // positive index 0..8191
    float my = ss[i];
    unsigned int cnt = 0;
    #pragma unroll 4
    for (int j = 0; j < NS; j++) {
        float v = ss[j];
        cnt += (v < my) || (v == my && j < i);
    }
    #pragma unroll
    for (int off = 16; off > 0; off >>= 1)
        cnt += __shfl_xor_sync(0xffffffffu, cnt, off);
    if ((tid & 31) == 0) atomicAdd(R, cnt);
}

__global__ void auc_final_kernel(const unsigned int* __restrict__ R, float* __restrict__ out) {
    double r = (double)(*R);
    double npos = (double)NP, nneg = (double)NP;
    out[0] = (float)((r - npos * (npos - 1.0) * 0.5) / (npos * nneg));
}

// ---------------------------------------------------------------------------
// Launch
// ---------------------------------------------------------------------------
extern "C" void kernel_launch(void* const* d_in, const int* in_sizes, int n_in,
                              void* d_out, int out_size) {
    const int*   src0_id   = (const int*)  d_in[0];
    const int*   src0_cats = (const int*)  d_in[1];
    const float* src0_genre= (const float*)d_in[2];
    const int*   es0       = (const int*)  d_in[3];
    const int*   ed0       = (const int*)  d_in[4];
    const float* w0        = (const float*)d_in[5];
    const int*   es1       = (const int*)  d_in[6];
    const int*   ed1       = (const int*)  d_in[7];
    const float* w1        = (const float*)d_in[8];
    const int*   pos_src   = (const int*)  d_in[9];
    const int*   pos_dst   = (const int*)  d_in[10];
    const int*   neg_src   = (const int*)  d_in[11];
    const int*   neg_dst   = (const int*)  d_in[12];
    const int*   seed_nids = (const int*)  d_in[13];
    const float* track_emb = (const float*)d_in[14];
    const float* cat_embs  = (const float*)d_in[15];
    const float* fc_W      = (const float*)d_in[16];
    const float* fc_b      = (const float*)d_in[17];
    const float* Q0_W      = (const float*)d_in[18];
    const float* Q0_b      = (const float*)d_in[19];
    const float* W0_W      = (const float*)d_in[20];
    const float* W0_b      = (const float*)d_in[21];
    const float* Q1_W      = (const float*)d_in[22];
    const float* Q1_b      = (const float*)d_in[23];
    const float* W1_W      = (const float*)d_in[24];
    const float* W1_b      = (const float*)d_in[25];
    const float* bias      = (const float*)d_in[26];
    float* out = (float*)d_out;

    // Resolve device addresses of scratch symbols (pure lookup, capture-safe).
    float *p_h, *p_n, *p_agg0, *p_ws0, *p_inv0, *p_h1, *p_agg1, *p_ws1, *p_inv1, *p_hitem, *p_scores;
    unsigned int* p_R;
    cudaGetSymbolAddress((void**)&p_h,     g_h);
    cudaGetSymbolAddress((void**)&p_n,     g_n);
    cudaGetSymbolAddress((void**)&p_agg0,  g_agg0);
    cudaGetSymbolAddress((void**)&p_ws0,   g_ws0);
    cudaGetSymbolAddress((void**)&p_inv0,  g_inv0);
    cudaGetSymbolAddress((void**)&p_h1,    g_h1);
    cudaGetSymbolAddress((void**)&p_agg1,  g_agg1);
    cudaGetSymbolAddress((void**)&p_ws1,   g_ws1);
    cudaGetSymbolAddress((void**)&p_inv1,  g_inv1);
    cudaGetSymbolAddress((void**)&p_hitem, g_hitem);
    cudaGetSymbolAddress((void**)&p_scores,g_scores);
    cudaGetSymbolAddress((void**)&p_R,     g_rank_sum);

    // Zero accumulators
    zero_f_kernel<<<4096, 256>>>(p_agg0, N_DST0 * HID);
    zero_f_kernel<<<64, 256>>>(p_ws0, N_DST0);
    zero_f_kernel<<<512, 256>>>(p_agg1, N_DST1 * HID);
    zero_f_kernel<<<8, 256>>>(p_ws1, N_DST1);
    zero_u32_kernel<<<1, 1>>>(p_R);

    // 1) projection
    proj_kernel<<<N_SRC0 / BM, 256>>>(src0_id, src0_cats, src0_genre,
                                      cat_embs, fc_W, fc_b, track_emb, p_h);

    // 2) layer 0
    gemm_q_kernel<<<N_SRC0 / BM, 256>>>(p_h, Q0_W, Q0_b, p_n);
    edge_agg_kernel<<<NE0 / 8, 256>>>(p_n, es0, ed0, w0, p_agg0, p_ws0, NE0);
    invws_kernel<<<(N_DST0 + 255) / 256, 256>>>(p_ws0, p_inv0, N_DST0);
    gemm_wnorm_kernel<<<N_DST0 / BM, 256>>>(p_agg0, p_inv0, p_h, W0_W, W0_b,
                                            nullptr, p_h1);

    // 3) layer 1
    gemm_q_kernel<<<N_DST0 / BM, 256>>>(p_h1, Q1_W, Q1_b, p_n);
    edge_agg_kernel<<<NE1 / 8, 256>>>(p_n, es1, ed1, w1, p_agg1, p_ws1, NE1);
    invws_kernel<<<(N_DST1 + 255) / 256, 256>>>(p_ws1, p_inv1, N_DST1);
    gemm_wnorm_kernel<<<N_DST1 / BM, 256>>>(p_agg1, p_inv1, p_h1, W1_W, W1_b,
                                            p_h /* + h[:8192] residual */, p_hitem);

    // 4) scores, loss, AUC
    score_kernel<<<NS / 8, 256>>>(p_hitem, pos_src, pos_dst, neg_src, neg_dst,
                                  seed_nids, bias, p_scores);
    loss_kernel<<<NP / 256, 256>>>(p_scores, out);

    cudaFuncSetAttribute(auc_count_kernel,
                         cudaFuncAttributeMaxDynamicSharedMemorySize, NS * sizeof(float));
    auc_count_kernel<<<NP / 256, 256, NS * sizeof(float)>>>(p_scores, p_R);
    if (out_size >= NP + 1)
        auc_final_kernel<<<1, 1>>>(p_R, out + NP);
}

// round 3
// speedup vs baseline: 1.5492x; 1.5492x over previous
#include <cuda_runtime.h>
#include <cuda_bf16.h>
#include <math.h>

// ---------------------------------------------------------------------------
// Problem constants
// ---------------------------------------------------------------------------
#define N_SRC0   262144
#define N_DST0   65536
#define N_DST1   8192
#define HID      128
#define N_CATS   9
#define CAT_VOCAB 101
#define CAT_DIM  16
#define GENRE_DIM 20
#define NE0      1048576
#define NE1      131072
#define NP       8192
#define NS       16384

// ---------------------------------------------------------------------------
// Static device scratch
// ---------------------------------------------------------------------------
__device__ float g_T[N_CATS * CAT_VOCAB * HID];   // cat-embedding projection table
__device__ float g_h[(size_t)N_SRC0 * HID];
__device__ float g_n[(size_t)N_SRC0 * HID];
__device__ float g_agg0[(size_t)N_DST0 * HID];
__device__ float g_ws0[N_DST0];
__device__ float g_h1[(size_t)N_DST0 * HID];
__device__ float g_agg1[(size_t)N_DST1 * HID];
__device__ float g_ws1[N_DST1];
__device__ float g_hitem[(size_t)N_DST1 * HID];
__device__ float g_scores[NS];
__device__ unsigned int g_rank_sum;

// ---------------------------------------------------------------------------
// Fused zero kernel (one launch)
// ---------------------------------------------------------------------------
__global__ void zero_all_kernel(float* agg0, float* ws0, float* agg1, float* ws1,
                                unsigned int* R) {
    int i = blockIdx.x * blockDim.x + threadIdx.x;
    int st = gridDim.x * blockDim.x;
    float4 z = {0.f, 0.f, 0.f, 0.f};
    for (int j = i; j < N_DST0 * HID / 4; j += st) ((float4*)agg0)[j] = z;
    for (int j = i; j < N_DST1 * HID / 4; j += st) ((float4*)agg1)[j] = z;
    for (int j = i; j < N_DST0; j += st) ws0[j] = 0.f;
    for (int j = i; j < N_DST1; j += st) ws1[j] = 0.f;
    if (i == 0) *R = 0u;
}

// ---------------------------------------------------------------------------
// Precompute T[c,v,:] = cat_embs[c,v,:] @ fc_W[16c:16c+16, :]
// grid = 909, block = 128 (thread = output col)
// ---------------------------------------------------------------------------
__global__ void precompute_T_kernel(const float* __restrict__ cat_embs,
                                    const float* __restrict__ fcW,
                                    float* __restrict__ T) {
    int cv = blockIdx.x;              // c*101 + v
    int c = cv / CAT_VOCAB;
    int n = threadIdx.x;
    const float* e = &cat_embs[cv * CAT_DIM];
    float acc = 0.f;
    #pragma unroll
    for (int d = 0; d < CAT_DIM; d++)
        acc += __ldg(&e[d]) * fcW[(c * CAT_DIM + d) * HID + n];
    T[cv * HID + n] = acc;
}

// ---------------------------------------------------------------------------
// proj: h = table-gather + genre @ fc_W[144:164] + fc_b + track_emb[ids]
// block = 256 (8 warps), 1 warp handles ROWS_PER_WARP rows
// ---------------------------------------------------------------------------
#define ROWS_PER_WARP 16
__global__ __launch_bounds__(256)
void proj_kernel(const int* __restrict__ ids,
                 const int* __restrict__ cats,
                 const float* __restrict__ genre,
                 const float* __restrict__ T,
                 const float* __restrict__ fcW,
                 const float* __restrict__ fcb,
                 const float* __restrict__ track_emb,
                 float* __restrict__ out) {
    int warp = threadIdx.x >> 5, lane = threadIdx.x & 31;
    float4 Wg[GENRE_DIM];
    #pragma unroll
    for (int g = 0; g < GENRE_DIM; g++)
        Wg[g] = *(const float4*)&fcW[(144 + g) * HID + lane * 4];
    float4 bb = *(const float4*)&fcb[lane * 4];

    int rbase = (blockIdx.x * 8 + warp) * ROWS_PER_WARP;
    for (int rr = 0; rr < ROWS_PER_WARP; rr++) {
        int r = rbase + rr;
        int myc = (lane < N_CATS) ? cats[r * N_CATS + lane] : 0;
        float gv = (lane < GENRE_DIM) ? genre[(size_t)r * GENRE_DIM + lane] : 0.f;
        int id = ids[r];
        float4 acc = bb;
        #pragma unroll
        for (int c = 0; c < N_CATS; c++) {
            int v = __shfl_sync(0xffffffffu, myc, c);
            float4 t = *(const float4*)&T[(c * CAT_VOCAB + v) * HID + lane * 4];
            acc.x += t.x; acc.y += t.y; acc.z += t.z; acc.w += t.w;
        }
        #pragma unroll
        for (int g = 0; g < GENRE_DIM; g++) {
            float s = __shfl_sync(0xffffffffu, gv, g);
            acc.x += s * Wg[g].x; acc.y += s * Wg[g].y;
            acc.z += s * Wg[g].z; acc.w += s * Wg[g].w;
        }
        float4 te = *(const float4*)&track_emb[(size_t)id * HID + lane * 4];
        acc.x += te.x; acc.y += te.y; acc.z += te.z; acc.w += te.w;
        *(float4*)&out[(size_t)r * HID + lane * 4] = acc;
    }
}

// ---------------------------------------------------------------------------
// GEMM config: 128x128 tile, BK=16, 256 threads, 8x8 micro-tile
// ---------------------------------------------------------------------------
#define GBM 128
#define GBN 128
#define GBK 16

// ---- Q GEMM: out = relu(A @ W + b), K = 128 -------------------------------
__global__ __launch_bounds__(256)
void gemm_q_kernel(const float* __restrict__ A,
                   const float* __restrict__ W,
                   const float* __restrict__ bvec,
                   float* __restrict__ out) {
    __shared__ float As[GBK][GBM];
    __shared__ float Ws[GBK][GBN];

    int tid = threadIdx.x;
    int tx = tid & 15, ty = tid >> 4;
    int r0 = blockIdx.x * GBM;
    const int K = 128;

    float acc[8][8] = {};

    for (int k0 = 0; k0 < K; k0 += GBK) {
        {
            int row = tid >> 1;
            int kq = (tid & 1) * 8;
            float4 v0 = *(const float4*)&A[(size_t)(r0 + row) * K + k0 + kq];
            float4 v1 = *(const float4*)&A[(size_t)(r0 + row) * K + k0 + kq + 4];
            As[kq + 0][row] = v0.x; As[kq + 1][row] = v0.y;
            As[kq + 2][row] = v0.z; As[kq + 3][row] = v0.w;
            As[kq + 4][row] = v1.x; As[kq + 5][row] = v1.y;
            As[kq + 6][row] = v1.z; As[kq + 7][row] = v1.w;
        }
        {
            int k = tid >> 4;
            int n = (tid & 15) * 8;
            *(float4*)&Ws[k][n]     = *(const float4*)&W[(k0 + k) * 128 + n];
            *(float4*)&Ws[k][n + 4] = *(const float4*)&W[(k0 + k) * 128 + n + 4];
        }
        __syncthreads();
        #pragma unroll
        for (int kk = 0; kk < GBK; kk++) {
            float4 a0 = *(float4*)&As[kk][ty * 8];
            float4 a1 = *(float4*)&As[kk][ty * 8 + 4];
            float4 b0 = *(float4*)&Ws[kk][tx * 8];
            float4 b1 = *(float4*)&Ws[kk][tx * 8 + 4];
            float ar[8] = {a0.x, a0.y, a0.z, a0.w, a1.x, a1.y, a1.z, a1.w};
            float bc[8] = {b0.x, b0.y, b0.z, b0.w, b1.x, b1.y, b1.z, b1.w};
            #pragma unroll
            for (int r = 0; r < 8; r++)
                #pragma unroll
                for (int c = 0; c < 8; c++)
                    acc[r][c] += ar[r] * bc[c];
        }
        __syncthreads();
    }

    float4 bv0 = *(const float4*)&bvec[tx * 8];
    float4 bv1 = *(const float4*)&bvec[tx * 8 + 4];
    float bv[8] = {bv0.x, bv0.y, bv0.z, bv0.w, bv1.x, bv1.y, bv1.z, bv1.w};
    #pragma unroll
    for (int r = 0; r < 8; r++) {
        size_t row = (size_t)(r0 + ty * 8 + r);
        float o[8];
        #pragma unroll
        for (int c = 0; c < 8; c++) o[c] = fmaxf(acc[r][c] + bv[c], 0.f);
        *(float4*)&out[row * 128 + tx * 8]     = *(float4*)&o[0];
        *(float4*)&out[row * 128 + tx * 8 + 4] = *(float4*)&o[4];
    }
}

// ---- W GEMM + row L2-normalize (+ optional residual), K = 256 --------------
__global__ __launch_bounds__(256)
void gemm_wnorm_kernel(const float* __restrict__ agg,
                       const float* __restrict__ ws,
                       const float* __restrict__ hdst,
                       const float* __restrict__ W,
                       const float* __restrict__ bvec,
                       const float* __restrict__ addsrc,
                       float* __restrict__ out) {
    __shared__ float As[GBK][GBM];
    __shared__ float Ws[GBK][GBN];

    int tid = threadIdx.x;
    int tx = tid & 15, ty = tid >> 4;
    int r0 = blockIdx.x * GBM;
    const int K = 256;

    int lrow = tid >> 1;
    int lkq  = (tid & 1) * 8;
    float iw = 1.0f / fmaxf(ws[r0 + lrow], 1.0f);

    float acc[8][8] = {};

    for (int k0 = 0; k0 < K; k0 += GBK) {
        {
            int kg = k0 + lkq;
            float4 v0, v1;
            if (kg < 128) {
                v0 = *(const float4*)&agg[(size_t)(r0 + lrow) * 128 + kg];
                v1 = *(const float4*)&agg[(size_t)(r0 + lrow) * 128 + kg + 4];
                v0.x *= iw; v0.y *= iw; v0.z *= iw; v0.w *= iw;
                v1.x *= iw; v1.y *= iw; v1.z *= iw; v1.w *= iw;
            } else {
                v0 = *(const float4*)&hdst[(size_t)(r0 + lrow) * 128 + (kg - 128)];
                v1 = *(const float4*)&hdst[(size_t)(r0 + lrow) * 128 + (kg - 128) + 4];
            }
            As[lkq + 0][lrow] = v0.x; As[lkq + 1][lrow] = v0.y;
            As[lkq + 2][lrow] = v0.z; As[lkq + 3][lrow] = v0.w;
            As[lkq + 4][lrow] = v1.x; As[lkq + 5][lrow] = v1.y;
            As[lkq + 6][lrow] = v1.z; As[lkq + 7][lrow] = v1.w;
        }
        {
            int k = tid >> 4;
            int n = (tid & 15) * 8;
            *(float4*)&Ws[k][n]     = *(const float4*)&W[(k0 + k) * 128 + n];
            *(float4*)&Ws[k][n + 4] = *(const float4*)&W[(k0 + k) * 128 + n + 4];
        }
        __syncthreads();
        #pragma unroll
        for (int kk = 0; kk < GBK; kk++) {
            float4 a0 = *(float4*)&As[kk][ty * 8];
            float4 a1 = *(float4*)&As[kk][ty * 8 + 4];
            float4 b0 = *(float4*)&Ws[kk][tx * 8];
            float4 b1 = *(float4*)&Ws[kk][tx * 8 + 4];
            float ar[8] = {a0.x, a0.y, a0.z, a0.w, a1.x, a1.y, a1.z, a1.w};
            float bc[8] = {b0.x, b0.y, b0.z, b0.w, b1.x, b1.y, b1.z, b1.w};
            #pragma unroll
            for (int r = 0; r < 8; r++)
                #pragma unroll
                for (int c = 0; c < 8; c++)
                    acc[r][c] += ar[r] * bc[c];
        }
        __syncthreads();
    }

    float4 bv0 = *(const float4*)&bvec[tx * 8];
    float4 bv1 = *(const float4*)&bvec[tx * 8 + 4];
    float bv[8] = {bv0.x, bv0.y, bv0.z, bv0.w, bv1.x, bv1.y, bv1.z, bv1.w};
    #pragma unroll
    for (int r = 0; r < 8; r++) {
        float z[8];
        float ss = 0.f;
        #pragma unroll
        for (int c = 0; c < 8; c++) {
            z[c] = fmaxf(acc[r][c] + bv[c], 0.f);
            ss += z[c] * z[c];
        }
        // reduce across the 16 lanes sharing this row (same ty)
        #pragma unroll
        for (int off = 8; off > 0; off >>= 1)
            ss += __shfl_xor_sync(0xffffffffu, ss, off);
        float invn = (ss > 0.f) ? rsqrtf(ss) : 1.0f;
        size_t row = (size_t)(r0 + ty * 8 + r);
        float o[8];
        #pragma unroll
        for (int c = 0; c < 8; c++) o[c] = z[c] * invn;
        if (addsrc) {
            float4 a0 = *(const float4*)&addsrc[row * 128 + tx * 8];
            float4 a1 = *(const float4*)&addsrc[row * 128 + tx * 8 + 4];
            o[0] += a0.x; o[1] += a0.y; o[2] += a0.z; o[3] += a0.w;
            o[4] += a1.x; o[5] += a1.y; o[6] += a1.z; o[7] += a1.w;
        }
        *(float4*)&out[row * 128 + tx * 8]     = *(float4*)&o[0];
        *(float4*)&out[row * 128 + tx * 8 + 4] = *(float4*)&o[4];
    }
}

// ---------------------------------------------------------------------------
// Edge aggregation: vector red.global.add.v4.f32 (sm_90+), 1 warp / edge
// ---------------------------------------------------------------------------
__global__ __launch_bounds__(256)
void edge_agg_kernel(const float* __restrict__ nmat,
                     const int* __restrict__ es,
                     const int* __restrict__ ed,
                     const float* __restrict__ w,
                     float* __restrict__ agg,
                     float* __restrict__ ws,
                     int nE) {
    int wid = (blockIdx.x * blockDim.x + threadIdx.x) >> 5;
    int lane = threadIdx.x & 31;
    if (wid >= nE) return;
    int s = __ldg(&es[wid]);
    int d = __ldg(&ed[wid]);
    float wt = __ldg(&w[wid]);
    float4 v = *(const float4*)&nmat[(size_t)s * 128 + lane * 4];
    float* dst = &agg[(size_t)d * 128 + lane * 4];
#if !defined(__CUDA_ARCH__) || __CUDA_ARCH__ >= 900
    asm volatile("red.global.add.v4.f32 [%0], {%1,%2,%3,%4};"
                 :: "l"(dst), "f"(v.x * wt), "f"(v.y * wt), "f"(v.z * wt), "f"(v.w * wt)
                 : "memory");
#else
    atomicAdd(dst + 0, v.x * wt);
    atomicAdd(dst + 1, v.y * wt);
    atomicAdd(dst + 2, v.z * wt);
    atomicAdd(dst + 3, v.w * wt);
#endif
    if (lane == 0) atomicAdd(&ws[d], wt);
}

// ---------------------------------------------------------------------------
// Scores: one warp per pair
// ---------------------------------------------------------------------------
__global__ __launch_bounds__(256)
void score_kernel(const float* __restrict__ hi,
                  const int* __restrict__ ps, const int* __restrict__ pd,
                  const int* __restrict__ ns, const int* __restrict__ nd,
                  const int* __restrict__ nids,
                  const float* __restrict__ bias,
                  float* __restrict__ scores) {
    int wid = (blockIdx.x * blockDim.x + threadIdx.x) >> 5;
    int lane = threadIdx.x & 31;
    if (wid >= NS) return;
    int s, d;
    if (wid < NP) { s = ps[wid]; d = pd[wid]; }
    else          { s = ns[wid - NP]; d = nd[wid - NP]; }
    float4 a = *(const float4*)&hi[(size_t)s * 128 + lane * 4];
    float4 b = *(const float4*)&hi[(size_t)d * 128 + lane * 4];
    float p = a.x * b.x + a.y * b.y + a.z * b.z + a.w * b.w;
    #pragma unroll
    for (int off = 16; off > 0; off >>= 1)
        p += __shfl_xor_sync(0xffffffffu, p, off);
    if (lane == 0)
        scores[wid] = p + bias[nids[s]] + bias[nids[d]];
}

__global__ void loss_kernel(const float* __restrict__ scores, float* __restrict__ out) {
    int i = blockIdx.x * blockDim.x + threadIdx.x;
    if (i < NP)
        out[i] = fmaxf(scores[NP + i] - scores[i] + 1.0f, 0.0f);
}

// ---------------------------------------------------------------------------
// AUC rank-sum (stable-sort semantics), 2D grid for parallelism
// ---------------------------------------------------------------------------
#define AUC_JCH 2048
__global__ __launch_bounds__(256)
void auc_count_kernel(const float* __restrict__ scores, unsigned int* __restrict__ R) {
    __shared__ float ss[AUC_JCH];
    int tid = threadIdx.x;
    int j0 = blockIdx.y * AUC_JCH;
    for (int j = tid; j < AUC_JCH; j += blockDim.x) ss[j] = scores[j0 + j];
    __syncthreads();
    int i = blockIdx.x * blockDim.x + tid;   // positive index 0..8191
    float my = scores[i];
    unsigned int cnt = 0;
    #pragma unroll 4
    for (int jj = 0; jj < AUC_JCH; jj++) {
        float v = ss[jj];
        int j = j0 + jj;
        cnt += (v < my) || (v == my && j < i);
    }
    #pragma unroll
    for (int off = 16; off > 0; off >>= 1)
        cnt += __shfl_xor_sync(0xffffffffu, cnt, off);
    if ((tid & 31) == 0) atomicAdd(R, cnt);
}

__global__ void auc_final_kernel(const unsigned int* __restrict__ R, float* __restrict__ out) {
    double r = (double)(*R);
    double npos = (double)NP, nneg = (double)NP;
    out[0] = (float)((r - npos * (npos - 1.0) * 0.5) / (npos * nneg));
}

// ---------------------------------------------------------------------------
// Launch
// ---------------------------------------------------------------------------
extern "C" void kernel_launch(void* const* d_in, const int* in_sizes, int n_in,
                              void* d_out, int out_size) {
    const int*   src0_id   = (const int*)  d_in[0];
    const int*   src0_cats = (const int*)  d_in[1];
    const float* src0_genre= (const float*)d_in[2];
    const int*   es0       = (const int*)  d_in[3];
    const int*   ed0       = (const int*)  d_in[4];
    const float* w0        = (const float*)d_in[5];
    const int*   es1       = (const int*)  d_in[6];
    const int*   ed1       = (const int*)  d_in[7];
    const float* w1        = (const float*)d_in[8];
    const int*   pos_src   = (const int*)  d_in[9];
    const int*   pos_dst   = (const int*)  d_in[10];
    const int*   neg_src   = (const int*)  d_in[11];
    const int*   neg_dst   = (const int*)  d_in[12];
    const int*   seed_nids = (const int*)  d_in[13];
    const float* track_emb = (const float*)d_in[14];
    const float* cat_embs  = (const float*)d_in[15];
    const float* fc_W      = (const float*)d_in[16];
    const float* fc_b      = (const float*)d_in[17];
    const float* Q0_W      = (const float*)d_in[18];
    const float* Q0_b      = (const float*)d_in[19];
    const float* W0_W      = (const float*)d_in[20];
    const float* W0_b      = (const float*)d_in[21];
    const float* Q1_W      = (const float*)d_in[22];
    const float* Q1_b      = (const float*)d_in[23];
    const float* W1_W      = (const float*)d_in[24];
    const float* W1_b      = (const float*)d_in[25];
    const float* bias      = (const float*)d_in[26];
    float* out = (float*)d_out;

    float *p_T, *p_h, *p_n, *p_agg0, *p_ws0, *p_h1, *p_agg1, *p_ws1, *p_hitem, *p_scores;
    unsigned int* p_R;
    cudaGetSymbolAddress((void**)&p_T,     g_T);
    cudaGetSymbolAddress((void**)&p_h,     g_h);
    cudaGetSymbolAddress((void**)&p_n,     g_n);
    cudaGetSymbolAddress((void**)&p_agg0,  g_agg0);
    cudaGetSymbolAddress((void**)&p_ws0,   g_ws0);
    cudaGetSymbolAddress((void**)&p_h1,    g_h1);
    cudaGetSymbolAddress((void**)&p_agg1,  g_agg1);
    cudaGetSymbolAddress((void**)&p_ws1,   g_ws1);
    cudaGetSymbolAddress((void**)&p_hitem, g_hitem);
    cudaGetSymbolAddress((void**)&p_scores,g_scores);
    cudaGetSymbolAddress((void**)&p_R,     g_rank_sum);

    // Launch order chosen so ncu (-s 5 -c 1) captures gemm_wnorm0 (#6)
    zero_all_kernel<<<1024, 256>>>(p_agg0, p_ws0, p_agg1, p_ws1, p_R);                   // 1
    precompute_T_kernel<<<N_CATS * CAT_VOCAB, 128>>>(cat_embs, fc_W, p_T);               // 2
    proj_kernel<<<N_SRC0 / (8 * ROWS_PER_WARP), 256>>>(src0_id, src0_cats, src0_genre,   // 3
                                                       p_T, fc_W, fc_b, track_emb, p_h);
    gemm_q_kernel<<<N_SRC0 / GBM, 256>>>(p_h, Q0_W, Q0_b, p_n);                          // 4
    edge_agg_kernel<<<NE0 / 8, 256>>>(p_n, es0, ed0, w0, p_agg0, p_ws0, NE0);            // 5
    gemm_wnorm_kernel<<<N_DST0 / GBM, 256>>>(p_agg0, p_ws0, p_h, W0_W, W0_b,             // 6 (ncu)
                                             nullptr, p_h1);

    gemm_q_kernel<<<N_DST0 / GBM, 256>>>(p_h1, Q1_W, Q1_b, p_n);
    edge_agg_kernel<<<NE1 / 8, 256>>>(p_n, es1, ed1, w1, p_agg1, p_ws1, NE1);
    gemm_wnorm_kernel<<<N_DST1 / GBM, 256>>>(p_agg1, p_ws1, p_h1, W1_W, W1_b,
                                             p_h /* residual h[:8192] */, p_hitem);

    score_kernel<<<NS / 8, 256>>>(p_hitem, pos_src, pos_dst, neg_src, neg_dst,
                                  seed_nids, bias, p_scores);
    loss_kernel<<<NP / 256, 256>>>(p_scores, out);

    dim3 auc_grid(NP / 256, NS / AUC_JCH);
    auc_count_kernel<<<auc_grid, 256>>>(p_scores, p_R);
    if (out_size >= NP + 1)
        auc_final_kernel<<<1, 1>>>(p_R, out + NP);
}

// round 4
// speedup vs baseline: 1.7425x; 1.1248x over previous
#include <cuda_runtime.h>
#include <cuda_bf16.h>
#include <math.h>

// ---------------------------------------------------------------------------
// Problem constants
// ---------------------------------------------------------------------------
#define N_SRC0   262144
#define N_DST0   65536
#define N_DST1   8192
#define HID      128
#define N_CATS   9
#define CAT_VOCAB 101
#define CAT_DIM  16
#define GENRE_DIM 20
#define NE0      1048576
#define NE1      131072
#define NP       8192
#define NS       16384

// ---------------------------------------------------------------------------
// Static device scratch
// ---------------------------------------------------------------------------
__device__ float g_T[N_CATS * CAT_VOCAB * HID];
__device__ float g_h[(size_t)N_SRC0 * HID];
__device__ float g_n[(size_t)N_SRC0 * HID];
__device__ float g_agg0[(size_t)N_DST0 * HID];
__device__ float g_ws0[N_DST0];
__device__ float g_h1[(size_t)N_DST0 * HID];
__device__ float g_agg1[(size_t)N_DST1 * HID];
__device__ float g_ws1[N_DST1];
__device__ float g_hitem[(size_t)N_DST1 * HID];
__device__ float g_scores[NS];
__device__ unsigned int g_rank_sum;

// ---------------------------------------------------------------------------
// tf32 helpers
// ---------------------------------------------------------------------------
__device__ __forceinline__ unsigned f2tf32(float f) {
    unsigned u;
    asm("cvt.rna.tf32.f32 %0, %1;" : "=r"(u) : "f"(f));
    return u;
}
__device__ __forceinline__ void split_tf32(float f, unsigned& hi, unsigned& lo) {
    hi = f2tf32(f);
    float r = f - __uint_as_float(hi);
    lo = f2tf32(r);
}
__device__ __forceinline__ void mma_tf32(float* c, const unsigned* a, const unsigned* b) {
    asm volatile(
        "mma.sync.aligned.m16n8k8.row.col.f32.tf32.tf32.f32 "
        "{%0,%1,%2,%3}, {%4,%5,%6,%7}, {%8,%9}, {%0,%1,%2,%3};"
        : "+f"(c[0]), "+f"(c[1]), "+f"(c[2]), "+f"(c[3])
        : "r"(a[0]), "r"(a[1]), "r"(a[2]), "r"(a[3]), "r"(b[0]), "r"(b[1]));
}

// ---------------------------------------------------------------------------
// Shared GEMM core: 128x128 block tile, K-step 16, 8 warps (4x2),
// warp tile 32x64, tf32x3 via m16n8k8.
// smem layouts: As[m][k] stride 20 (pad 4), Bs[k][n] stride 136 (pad 8).
// ---------------------------------------------------------------------------
#define A_STR 20
#define B_STR 136

__device__ __forceinline__ void tile_compute(const float* __restrict__ As,
                                             const float* __restrict__ Bs,
                                             float acc[2][8][4],
                                             int g, int t, int warp_m, int warp_n) {
    #pragma unroll
    for (int ks = 0; ks < 2; ks++) {
        int kb = ks * 8;
        unsigned ahi[2][4], alo[2][4];
        #pragma unroll
        for (int mi = 0; mi < 2; mi++) {
            int rb = warp_m * 32 + mi * 16 + g;
            float a0 = As[rb * A_STR + kb + t];
            float a1 = As[(rb + 8) * A_STR + kb + t];
            float a2 = As[rb * A_STR + kb + t + 4];
            float a3 = As[(rb + 8) * A_STR + kb + t + 4];
            split_tf32(a0, ahi[mi][0], alo[mi][0]);
            split_tf32(a1, ahi[mi][1], alo[mi][1]);
            split_tf32(a2, ahi[mi][2], alo[mi][2]);
            split_tf32(a3, ahi[mi][3], alo[mi][3]);
        }
        #pragma unroll
        for (int ni = 0; ni < 8; ni++) {
            int n0 = warp_n * 64 + ni * 8 + g;
            float b0 = Bs[(kb + t) * B_STR + n0];
            float b1 = Bs[(kb + t + 4) * B_STR + n0];
            unsigned bh[2], bl[2];
            split_tf32(b0, bh[0], bl[0]);
            split_tf32(b1, bh[1], bl[1]);
            #pragma unroll
            for (int mi = 0; mi < 2; mi++) {
                mma_tf32(acc[mi][ni], ahi[mi], bh);
                mma_tf32(acc[mi][ni], alo[mi], bh);
                mma_tf32(acc[mi][ni], ahi[mi], bl);
            }
        }
    }
}

// ---- Q GEMM: out = relu(A @ W + b), K = 128, tensor tf32x3 -----------------
__global__ __launch_bounds__(256, 2)
void gemm_q_kernel(const float* __restrict__ A,
                   const float* __restrict__ W,
                   const float* __restrict__ bvec,
                   float* __restrict__ out) {
    __shared__ float As[2][128 * A_STR];
    __shared__ float Bs[2][16 * B_STR];

    const int K = 128;
    const int NIT = K / 16;
    int tid = threadIdx.x;
    int wid = tid >> 5, lane = tid & 31;
    int g = lane >> 2, t = lane & 3;
    int warp_m = wid & 3, warp_n = wid >> 2;
    int r0 = blockIdx.x * 128;

    int lr = tid >> 1;             // load row 0..127
    int lkq = (tid & 1) * 8;       // k offset 0 or 8
    int bk = tid >> 4;             // B load k 0..15
    int bn = (tid & 15) * 8;       // B load n

    float acc[2][8][4] = {};

    // prologue: tile 0
    float4 ra0 = *(const float4*)&A[(size_t)(r0 + lr) * K + lkq];
    float4 ra1 = *(const float4*)&A[(size_t)(r0 + lr) * K + lkq + 4];
    float4 rb0 = *(const float4*)&W[bk * 128 + bn];
    float4 rb1 = *(const float4*)&W[bk * 128 + bn + 4];
    *(float4*)&As[0][lr * A_STR + lkq]     = ra0;
    *(float4*)&As[0][lr * A_STR + lkq + 4] = ra1;
    *(float4*)&Bs[0][bk * B_STR + bn]     = rb0;
    *(float4*)&Bs[0][bk * B_STR + bn + 4] = rb1;
    __syncthreads();

    for (int it = 0; it < NIT; it++) {
        if (it + 1 < NIT) {
            int k0 = (it + 1) * 16;
            ra0 = *(const float4*)&A[(size_t)(r0 + lr) * K + k0 + lkq];
            ra1 = *(const float4*)&A[(size_t)(r0 + lr) * K + k0 + lkq + 4];
            rb0 = *(const float4*)&W[(k0 + bk) * 128 + bn];
            rb1 = *(const float4*)&W[(k0 + bk) * 128 + bn + 4];
        }
        tile_compute(As[it & 1], Bs[it & 1], acc, g, t, warp_m, warp_n);
        if (it + 1 < NIT) {
            int b = (it + 1) & 1;
            *(float4*)&As[b][lr * A_STR + lkq]     = ra0;
            *(float4*)&As[b][lr * A_STR + lkq + 4] = ra1;
            *(float4*)&Bs[b][bk * B_STR + bn]     = rb0;
            *(float4*)&Bs[b][bk * B_STR + bn + 4] = rb1;
        }
        __syncthreads();
    }

    // epilogue: bias + relu
    #pragma unroll
    for (int ni = 0; ni < 8; ni++) {
        int col = warp_n * 64 + ni * 8 + 2 * t;
        float2 bv = *(const float2*)&bvec[col];
        #pragma unroll
        for (int mi = 0; mi < 2; mi++) {
            int row0 = r0 + warp_m * 32 + mi * 16 + g;
            float2 o0, o1;
            o0.x = fmaxf(acc[mi][ni][0] + bv.x, 0.f);
            o0.y = fmaxf(acc[mi][ni][1] + bv.y, 0.f);
            o1.x = fmaxf(acc[mi][ni][2] + bv.x, 0.f);
            o1.y = fmaxf(acc[mi][ni][3] + bv.y, 0.f);
            *(float2*)&out[(size_t)row0 * 128 + col]       = o0;
            *(float2*)&out[(size_t)(row0 + 8) * 128 + col] = o1;
        }
    }
}

// ---- W GEMM + row L2-normalize (+ optional residual), K = 256, tf32x3 ------
__global__ __launch_bounds__(256, 2)
void gemm_wnorm_kernel(const float* __restrict__ agg,
                       const float* __restrict__ ws,
                       const float* __restrict__ hdst,
                       const float* __restrict__ W,
                       const float* __restrict__ bvec,
                       const float* __restrict__ addsrc,
                       float* __restrict__ out) {
    __shared__ float As[2][128 * A_STR];
    __shared__ float Bs[2][16 * B_STR];
    __shared__ float Ss[128][2];

    const int K = 256;
    const int NIT = K / 16;
    int tid = threadIdx.x;
    int wid = tid >> 5, lane = tid & 31;
    int g = lane >> 2, t = lane & 3;
    int warp_m = wid & 3, warp_n = wid >> 2;
    int r0 = blockIdx.x * 128;

    int lr = tid >> 1;
    int lkq = (tid & 1) * 8;
    int bk = tid >> 4;
    int bn = (tid & 15) * 8;

    float iw = 1.0f / fmaxf(ws[r0 + lr], 1.0f);

    float acc[2][8][4] = {};

    // A-tile builder: cols <128 come from agg*iw, cols >=128 from hdst
    auto loadA = [&](int kg, float4& v0, float4& v1) {
        if (kg < 128) {
            v0 = *(const float4*)&agg[(size_t)(r0 + lr) * 128 + kg];
            v1 = *(const float4*)&agg[(size_t)(r0 + lr) * 128 + kg + 4];
            v0.x *= iw; v0.y *= iw; v0.z *= iw; v0.w *= iw;
            v1.x *= iw; v1.y *= iw; v1.z *= iw; v1.w *= iw;
        } else {
            v0 = *(const float4*)&hdst[(size_t)(r0 + lr) * 128 + (kg - 128)];
            v1 = *(const float4*)&hdst[(size_t)(r0 + lr) * 128 + (kg - 128) + 4];
        }
    };

    float4 ra0, ra1, rb0, rb1;
    loadA(lkq, ra0, ra1);
    rb0 = *(const float4*)&W[bk * 128 + bn];
    rb1 = *(const float4*)&W[bk * 128 + bn + 4];
    *(float4*)&As[0][lr * A_STR + lkq]     = ra0;
    *(float4*)&As[0][lr * A_STR + lkq + 4] = ra1;
    *(float4*)&Bs[0][bk * B_STR + bn]     = rb0;
    *(float4*)&Bs[0][bk * B_STR + bn + 4] = rb1;
    __syncthreads();

    for (int it = 0; it < NIT; it++) {
        if (it + 1 < NIT) {
            int k0 = (it + 1) * 16;
            loadA(k0 + lkq, ra0, ra1);
            rb0 = *(const float4*)&W[(k0 + bk) * 128 + bn];
            rb1 = *(const float4*)&W[(k0 + bk) * 128 + bn + 4];
        }
        tile_compute(As[it & 1], Bs[it & 1], acc, g, t, warp_m, warp_n);
        if (it + 1 < NIT) {
            int b = (it + 1) & 1;
            *(float4*)&As[b][lr * A_STR + lkq]     = ra0;
            *(float4*)&As[b][lr * A_STR + lkq + 4] = ra1;
            *(float4*)&Bs[b][bk * B_STR + bn]     = rb0;
            *(float4*)&Bs[b][bk * B_STR + bn + 4] = rb1;
        }
        __syncthreads();
    }

    // ---- epilogue: z = relu(acc + bias); per-row L2 norm; +residual --------
    // 1) bias+relu, stash into acc; accumulate ss per (mi, half)
    float ssl[2][2] = {};
    #pragma unroll
    for (int ni = 0; ni < 8; ni++) {
        int col = warp_n * 64 + ni * 8 + 2 * t;
        float2 bv = *(const float2*)&bvec[col];
        #pragma unroll
        for (int mi = 0; mi < 2; mi++) {
            float z0 = fmaxf(acc[mi][ni][0] + bv.x, 0.f);
            float z1 = fmaxf(acc[mi][ni][1] + bv.y, 0.f);
            float z2 = fmaxf(acc[mi][ni][2] + bv.x, 0.f);
            float z3 = fmaxf(acc[mi][ni][3] + bv.y, 0.f);
            acc[mi][ni][0] = z0; acc[mi][ni][1] = z1;
            acc[mi][ni][2] = z2; acc[mi][ni][3] = z3;
            ssl[mi][0] += z0 * z0 + z1 * z1;
            ssl[mi][1] += z2 * z2 + z3 * z3;
        }
    }
    // 2) reduce across the 4 lanes of the quad (same row)
    #pragma unroll
    for (int mi = 0; mi < 2; mi++)
        #pragma unroll
        for (int h = 0; h < 2; h++) {
            float s = ssl[mi][h];
            s += __shfl_xor_sync(0xffffffffu, s, 1);
            s += __shfl_xor_sync(0xffffffffu, s, 2);
            ssl[mi][h] = s;
        }
    // 3) cross-warp_n reduce via smem
    if (t == 0) {
        #pragma unroll
        for (int mi = 0; mi < 2; mi++) {
            int r = warp_m * 32 + mi * 16 + g;
            Ss[r][warp_n]     = ssl[mi][0];
            Ss[r + 8][warp_n] = ssl[mi][1];
        }
    }
    __syncthreads();
    // 4) normalize + residual + store
    #pragma unroll
    for (int mi = 0; mi < 2; mi++) {
        int rl0 = warp_m * 32 + mi * 16 + g;
        float ss0 = Ss[rl0][0] + Ss[rl0][1];
        float ss1 = Ss[rl0 + 8][0] + Ss[rl0 + 8][1];
        float in0 = (ss0 > 0.f) ? rsqrtf(ss0) : 1.0f;
        float in1 = (ss1 > 0.f) ? rsqrtf(ss1) : 1.0f;
        size_t row0 = (size_t)(r0 + rl0);
        #pragma unroll
        for (int ni = 0; ni < 8; ni++) {
            int col = warp_n * 64 + ni * 8 + 2 * t;
            float2 o0, o1;
            o0.x = acc[mi][ni][0] * in0; o0.y = acc[mi][ni][1] * in0;
            o1.x = acc[mi][ni][2] * in1; o1.y = acc[mi][ni][3] * in1;
            if (addsrc) {
                float2 a0 = *(const float2*)&addsrc[row0 * 128 + col];
                float2 a1 = *(const float2*)&addsrc[(row0 + 8) * 128 + col];
                o0.x += a0.x; o0.y += a0.y;
                o1.x += a1.x; o1.y += a1.y;
            }
            *(float2*)&out[row0 * 128 + col]       = o0;
            *(float2*)&out[(row0 + 8) * 128 + col] = o1;
        }
    }
}

// ---------------------------------------------------------------------------
// Fused zero kernel
// ---------------------------------------------------------------------------
__global__ void zero_all_kernel(float* agg0, float* ws0, float* agg1, float* ws1,
                                unsigned int* R) {
    int i = blockIdx.x * blockDim.x + threadIdx.x;
    int st = gridDim.x * blockDim.x;
    float4 z = {0.f, 0.f, 0.f, 0.f};
    for (int j = i; j < N_DST0 * HID / 4; j += st) ((float4*)agg0)[j] = z;
    for (int j = i; j < N_DST1 * HID / 4; j += st) ((float4*)agg1)[j] = z;
    for (int j = i; j < N_DST0; j += st) ws0[j] = 0.f;
    for (int j = i; j < N_DST1; j += st) ws1[j] = 0.f;
    if (i == 0) *R = 0u;
}

// ---------------------------------------------------------------------------
// Precompute T[c,v,:] = cat_embs[c,v,:] @ fc_W[16c:16c+16, :]
// ---------------------------------------------------------------------------
__global__ void precompute_T_kernel(const float* __restrict__ cat_embs,
                                    const float* __restrict__ fcW,
                                    float* __restrict__ T) {
    int cv = blockIdx.x;
    int c = cv / CAT_VOCAB;
    int n = threadIdx.x;
    const float* e = &cat_embs[cv * CAT_DIM];
    float acc = 0.f;
    #pragma unroll
    for (int d = 0; d < CAT_DIM; d++)
        acc += __ldg(&e[d]) * fcW[(c * CAT_DIM + d) * HID + n];
    T[cv * HID + n] = acc;
}

// ---------------------------------------------------------------------------
// proj
// ---------------------------------------------------------------------------
#define ROWS_PER_WARP 16
__global__ __launch_bounds__(256)
void proj_kernel(const int* __restrict__ ids,
                 const int* __restrict__ cats,
                 const float* __restrict__ genre,
                 const float* __restrict__ T,
                 const float* __restrict__ fcW,
                 const float* __restrict__ fcb,
                 const float* __restrict__ track_emb,
                 float* __restrict__ out) {
    int warp = threadIdx.x >> 5, lane = threadIdx.x & 31;
    float4 Wg[GENRE_DIM];
    #pragma unroll
    for (int g = 0; g < GENRE_DIM; g++)
        Wg[g] = *(const float4*)&fcW[(144 + g) * HID + lane * 4];
    float4 bb = *(const float4*)&fcb[lane * 4];

    int rbase = (blockIdx.x * 8 + warp) * ROWS_PER_WARP;
    for (int rr = 0; rr < ROWS_PER_WARP; rr++) {
        int r = rbase + rr;
        int myc = (lane < N_CATS) ? cats[r * N_CATS + lane] : 0;
        float gv = (lane < GENRE_DIM) ? genre[(size_t)r * GENRE_DIM + lane] : 0.f;
        int id = ids[r];
        float4 acc = bb;
        #pragma unroll
        for (int c = 0; c < N_CATS; c++) {
            int v = __shfl_sync(0xffffffffu, myc, c);
            float4 t = *(const float4*)&T[(c * CAT_VOCAB + v) * HID + lane * 4];
            acc.x += t.x; acc.y += t.y; acc.z += t.z; acc.w += t.w;
        }
        #pragma unroll
        for (int g = 0; g < GENRE_DIM; g++) {
            float s = __shfl_sync(0xffffffffu, gv, g);
            acc.x += s * Wg[g].x; acc.y += s * Wg[g].y;
            acc.z += s * Wg[g].z; acc.w += s * Wg[g].w;
        }
        float4 te = *(const float4*)&track_emb[(size_t)id * HID + lane * 4];
        acc.x += te.x; acc.y += te.y; acc.z += te.z; acc.w += te.w;
        *(float4*)&out[(size_t)r * HID + lane * 4] = acc;
    }
}

// ---------------------------------------------------------------------------
// Edge aggregation: vector red.global.add.v4.f32 (sm_90+), 1 warp / edge
// ---------------------------------------------------------------------------
__global__ __launch_bounds__(256)
void edge_agg_kernel(const float* __restrict__ nmat,
                     const int* __restrict__ es,
                     const int* __restrict__ ed,
                     const float* __restrict__ w,
                     float* __restrict__ agg,
                     float* __restrict__ ws,
                     int nE) {
    int wid = (blockIdx.x * blockDim.x + threadIdx.x) >> 5;
    int lane = threadIdx.x & 31;
    if (wid >= nE) return;
    int s = __ldg(&es[wid]);
    int d = __ldg(&ed[wid]);
    float wt = __ldg(&w[wid]);
    float4 v = *(const float4*)&nmat[(size_t)s * 128 + lane * 4];
    float* dst = &agg[(size_t)d * 128 + lane * 4];
#if !defined(__CUDA_ARCH__) || __CUDA_ARCH__ >= 900
    asm volatile("red.global.add.v4.f32 [%0], {%1,%2,%3,%4};"
                 :: "l"(dst), "f"(v.x * wt), "f"(v.y * wt), "f"(v.z * wt), "f"(v.w * wt)
                 : "memory");
#else
    atomicAdd(dst + 0, v.x * wt);
    atomicAdd(dst + 1, v.y * wt);
    atomicAdd(dst + 2, v.z * wt);
    atomicAdd(dst + 3, v.w * wt);
#endif
    if (lane == 0) atomicAdd(&ws[d], wt);
}

// ---------------------------------------------------------------------------
// Scores / loss / AUC
// ---------------------------------------------------------------------------
__global__ __launch_bounds__(256)
void score_kernel(const float* __restrict__ hi,
                  const int* __restrict__ ps, const int* __restrict__ pd,
                  const int* __restrict__ ns, const int* __restrict__ nd,
                  const int* __restrict__ nids,
                  const float* __restrict__ bias,
                  float* __restrict__ scores) {
    int wid = (blockIdx.x * blockDim.x + threadIdx.x) >> 5;
    int lane = threadIdx.x & 31;
    if (wid >= NS) return;
    int s, d;
    if (wid < NP) { s = ps[wid]; d = pd[wid]; }
    else          { s = ns[wid - NP]; d = nd[wid - NP]; }
    float4 a = *(const float4*)&hi[(size_t)s * 128 + lane * 4];
    float4 b = *(const float4*)&hi[(size_t)d * 128 + lane * 4];
    float p = a.x * b.x + a.y * b.y + a.z * b.z + a.w * b.w;
    #pragma unroll
    for (int off = 16; off > 0; off >>= 1)
        p += __shfl_xor_sync(0xffffffffu, p, off);
    if (lane == 0)
        scores[wid] = p + bias[nids[s]] + bias[nids[d]];
}

__global__ void loss_kernel(const float* __restrict__ scores, float* __restrict__ out) {
    int i = blockIdx.x * blockDim.x + threadIdx.x;
    if (i < NP)
        out[i] = fmaxf(scores[NP + i] - scores[i] + 1.0f, 0.0f);
}

#define AUC_JCH 2048
__global__ __launch_bounds__(256)
void auc_count_kernel(const float* __restrict__ scores, unsigned int* __restrict__ R) {
    __shared__ float ss[AUC_JCH];
    int tid = threadIdx.x;
    int j0 = blockIdx.y * AUC_JCH;
    for (int j = tid; j < AUC_JCH; j += blockDim.x) ss[j] = scores[j0 + j];
    __syncthreads();
    int i = blockIdx.x * blockDim.x + tid;
    float my = scores[i];
    unsigned int cnt = 0;
    #pragma unroll 4
    for (int jj = 0; jj < AUC_JCH; jj++) {
        float v = ss[jj];
        int j = j0 + jj;
        cnt += (v < my) || (v == my && j < i);
    }
    #pragma unroll
    for (int off = 16; off > 0; off >>= 1)
        cnt += __shfl_xor_sync(0xffffffffu, cnt, off);
    if ((tid & 31) == 0) atomicAdd(R, cnt);
}

__global__ void auc_final_kernel(const unsigned int* __restrict__ R, float* __restrict__ out) {
    double r = (double)(*R);
    double npos = (double)NP, nneg = (double)NP;
    out[0] = (float)((r - npos * (npos - 1.0) * 0.5) / (npos * nneg));
}

// ---------------------------------------------------------------------------
// Launch
// ---------------------------------------------------------------------------
extern "C" void kernel_launch(void* const* d_in, const int* in_sizes, int n_in,
                              void* d_out, int out_size) {
    const int*   src0_id   = (const int*)  d_in[0];
    const int*   src0_cats = (const int*)  d_in[1];
    const float* src0_genre= (const float*)d_in[2];
    const int*   es0       = (const int*)  d_in[3];
    const int*   ed0       = (const int*)  d_in[4];
    const float* w0        = (const float*)d_in[5];
    const int*   es1       = (const int*)  d_in[6];
    const int*   ed1       = (const int*)  d_in[7];
    const float* w1        = (const float*)d_in[8];
    const int*   pos_src   = (const int*)  d_in[9];
    const int*   pos_dst   = (const int*)  d_in[10];
    const int*   neg_src   = (const int*)  d_in[11];
    const int*   neg_dst   = (const int*)  d_in[12];
    const int*   seed_nids = (const int*)  d_in[13];
    const float* track_emb = (const float*)d_in[14];
    const float* cat_embs  = (const float*)d_in[15];
    const float* fc_W      = (const float*)d_in[16];
    const float* fc_b      = (const float*)d_in[17];
    const float* Q0_W      = (const float*)d_in[18];
    const float* Q0_b      = (const float*)d_in[19];
    const float* W0_W      = (const float*)d_in[20];
    const float* W0_b      = (const float*)d_in[21];
    const float* Q1_W      = (const float*)d_in[22];
    const float* Q1_b      = (const float*)d_in[23];
    const float* W1_W      = (const float*)d_in[24];
    const float* W1_b      = (const float*)d_in[25];
    const float* bias      = (const float*)d_in[26];
    float* out = (float*)d_out;

    float *p_T, *p_h, *p_n, *p_agg0, *p_ws0, *p_h1, *p_agg1, *p_ws1, *p_hitem, *p_scores;
    unsigned int* p_R;
    cudaGetSymbolAddress((void**)&p_T,     g_T);
    cudaGetSymbolAddress((void**)&p_h,     g_h);
    cudaGetSymbolAddress((void**)&p_n,     g_n);
    cudaGetSymbolAddress((void**)&p_agg0,  g_agg0);
    cudaGetSymbolAddress((void**)&p_ws0,   g_ws0);
    cudaGetSymbolAddress((void**)&p_h1,    g_h1);
    cudaGetSymbolAddress((void**)&p_agg1,  g_agg1);
    cudaGetSymbolAddress((void**)&p_ws1,   g_ws1);
    cudaGetSymbolAddress((void**)&p_hitem, g_hitem);
    cudaGetSymbolAddress((void**)&p_scores,g_scores);
    cudaGetSymbolAddress((void**)&p_R,     g_rank_sum);

    // Launch order keeps ncu (-s 5 -c 1) on launch #6 = gemm_wnorm0 (new tensor kernel)
    zero_all_kernel<<<1024, 256>>>(p_agg0, p_ws0, p_agg1, p_ws1, p_R);                   // 1
    precompute_T_kernel<<<N_CATS * CAT_VOCAB, 128>>>(cat_embs, fc_W, p_T);               // 2
    proj_kernel<<<N_SRC0 / (8 * ROWS_PER_WARP), 256>>>(src0_id, src0_cats, src0_genre,   // 3
                                                       p_T, fc_W, fc_b, track_emb, p_h);
    gemm_q_kernel<<<N_SRC0 / 128, 256>>>(p_h, Q0_W, Q0_b, p_n);                          // 4
    edge_agg_kernel<<<NE0 / 8, 256>>>(p_n, es0, ed0, w0, p_agg0, p_ws0, NE0);            // 5
    gemm_wnorm_kernel<<<N_DST0 / 128, 256>>>(p_agg0, p_ws0, p_h, W0_W, W0_b,             // 6 (ncu)
                                             nullptr, p_h1);

    gemm_q_kernel<<<N_DST0 / 128, 256>>>(p_h1, Q1_W, Q1_b, p_n);
    edge_agg_kernel<<<NE1 / 8, 256>>>(p_n, es1, ed1, w1, p_agg1, p_ws1, NE1);
    gemm_wnorm_kernel<<<N_DST1 / 128, 256>>>(p_agg1, p_ws1, p_h1, W1_W, W1_b,
                                             p_h /* residual h[:8192] */, p_hitem);

    score_kernel<<<NS / 8, 256>>>(p_hitem, pos_src, pos_dst, neg_src, neg_dst,
                                  seed_nids, bias, p_scores);
    loss_kernel<<<NP / 256, 256>>>(p_scores, out);

    dim3 auc_grid(NP / 256, NS / AUC_JCH);
    auc_count_kernel<<<auc_grid, 256>>>(p_scores, p_R);
    if (out_size >= NP + 1)
        auc_final_kernel<<<1, 1>>>(p_R, out + NP);
}